// round 4
// baseline (speedup 1.0000x reference)
#include <cuda_runtime.h>
#include <math.h>

// Single-pass row normalization of two [32,1024,1024] fp32 tensors.
// One block (256 threads) per row of 1024 floats; each thread holds one
// float4 so the whole 4KB row stays register-resident between the degree
// reduction and the scaled store. HBM traffic = exactly 1R + 1W per element.
// Both tensors handled in ONE launch: blocks [0,32768) -> adj0,
// [32768,65536) -> adj1; output rows are the concatenated row space.

__global__ void __launch_bounds__(256, 8) row_norm_kernel(
    const float* __restrict__ in0, const float* __restrict__ in1,
    float* __restrict__ out)
{
    const long long gid = blockIdx.x;                   // 0 .. 65535
    const long long rows_per_tensor = 32768;
    const float* __restrict__ in = (gid < rows_per_tensor) ? in0 : in1;
    const long long row = gid & (rows_per_tensor - 1);  // row within tensor

    const float4* __restrict__ inrow =
        reinterpret_cast<const float4*>(in + row * 1024);

    // 256 threads x float4 = 1024 floats (whole row)
    float4 v = inrow[threadIdx.x];

    // thread-local partial
    float s = (v.x + v.y) + (v.z + v.w);

    // warp reduce
    #pragma unroll
    for (int o = 16; o > 0; o >>= 1)
        s += __shfl_xor_sync(0xffffffffu, s, o);

    __shared__ float warpsum[8];
    const int wid = threadIdx.x >> 5;
    const int lid = threadIdx.x & 31;
    if (lid == 0) warpsum[wid] = s;
    __syncthreads();

    // final reduce across the 8 warp partials (warp 0), broadcast via smem
    if (wid == 0) {
        float t = (lid < 8) ? warpsum[lid] : 0.0f;
        #pragma unroll
        for (int o = 4; o > 0; o >>= 1)
            t += __shfl_xor_sync(0xffffffffu, t, o);
        if (lid == 0) warpsum[0] = t;
    }
    __syncthreads();

    const float degree = warpsum[0];
    float inv = 1.0f / degree;
    // reference semantics: zero out non-finite inverse (degree == 0 rows)
    if (!isfinite(inv)) inv = 0.0f;

    float4 o4;
    o4.x = v.x * inv;
    o4.y = v.y * inv;
    o4.z = v.z * inv;
    o4.w = v.w * inv;

    reinterpret_cast<float4*>(out)[gid * 256 + threadIdx.x] = o4;
}

extern "C" void kernel_launch(void* const* d_in, const int* in_sizes, int n_in,
                              void* d_out, int out_size)
{
    const float* adj0 = (const float*)d_in[0];
    const float* adj1 = (const float*)d_in[1];
    float* out = (float*)d_out;

    row_norm_kernel<<<65536, 256>>>(adj0, adj1, out);
}

// round 5
// speedup vs baseline: 1.1072x; 1.1072x over previous
#include <cuda_runtime.h>
#include <math.h>

// One WARP per row of 1024 floats (two [32,1024,1024] fp32 tensors).
// Each lane loads 8 float4 (row fully register-resident, MLP=8 per thread),
// reduces the degree with warp shuffles only (no smem, no __syncthreads),
// then scales and streams the row back out. HBM traffic = 1R + 1W exactly.
// Blocks of 256 threads = 8 independent rows per block.
// Row ids [0,32768) -> adj0, [32768,65536) -> adj1; output is concatenated.

__global__ void __launch_bounds__(256) row_norm_warp_kernel(
    const float* __restrict__ in0, const float* __restrict__ in1,
    float* __restrict__ out)
{
    const int wid = threadIdx.x >> 5;
    const int lid = threadIdx.x & 31;
    const long long gid = (long long)blockIdx.x * 8 + wid;   // 0 .. 65535
    const long long rows_per_tensor = 32768;

    const float* __restrict__ in = (gid < rows_per_tensor) ? in0 : in1;
    const long long row = gid & (rows_per_tensor - 1);

    const float4* __restrict__ inrow =
        reinterpret_cast<const float4*>(in + row * 1024);

    // 8 independent streaming loads per lane: lane lid takes float4 slots
    // {lid, lid+32, ..., lid+224} -> each LDG.128 is a fully-coalesced
    // 512B warp transaction.
    float4 v[8];
    #pragma unroll
    for (int k = 0; k < 8; k++)
        v[k] = __ldcs(&inrow[k * 32 + lid]);

    // thread-local pairwise sum of 32 values
    float p[8];
    #pragma unroll
    for (int k = 0; k < 8; k++)
        p[k] = (v[k].x + v[k].y) + (v[k].z + v[k].w);
    float s = ((p[0] + p[1]) + (p[2] + p[3])) + ((p[4] + p[5]) + (p[6] + p[7]));

    // warp-only reduction (row sum lives in every lane afterwards)
    #pragma unroll
    for (int o = 16; o > 0; o >>= 1)
        s += __shfl_xor_sync(0xffffffffu, s, o);

    float inv = 1.0f / s;
    // reference semantics: zero out non-finite inverse (degree == 0 rows)
    if (!isfinite(inv)) inv = 0.0f;

    float4* __restrict__ outrow =
        reinterpret_cast<float4*>(out) + gid * 256;
    #pragma unroll
    for (int k = 0; k < 8; k++) {
        float4 o4;
        o4.x = v[k].x * inv;
        o4.y = v[k].y * inv;
        o4.z = v[k].z * inv;
        o4.w = v[k].w * inv;
        __stcs(&outrow[k * 32 + lid], o4);
    }
}

extern "C" void kernel_launch(void* const* d_in, const int* in_sizes, int n_in,
                              void* d_out, int out_size)
{
    const float* adj0 = (const float*)d_in[0];
    const float* adj1 = (const float*)d_in[1];
    float* out = (float*)d_out;

    // 65536 rows total, 8 rows (warps) per block
    row_norm_warp_kernel<<<8192, 256>>>(adj0, adj1, out);
}